// round 16
// baseline (speedup 1.0000x reference)
#include <cuda_runtime.h>

#define NH 8

// Per-head bilinear coefficient tensor (built on device; also copied to constant):
// g_C[h*81 + p*9 + q] = (C0,C1,C2,C3), ev_i = sum_{p,q} g01[p] * C_i[p][q] * g23[q]
__device__ __align__(16) float g_C[NH * 81 * 4];
__constant__ ulonglong2 c_C[NH * 81];   // .x=(C0,C1) packed, .y=(C2,C3) packed

// ---------------- packed f32x2 helpers ----------------
__device__ __forceinline__ unsigned long long pk2(float lo, float hi) {
    unsigned long long r;
    asm("mov.b64 %0, {%1, %2};" : "=l"(r) : "f"(lo), "f"(hi));
    return r;
}
__device__ __forceinline__ void fma2(unsigned long long& d,
                                     unsigned long long a,
                                     unsigned long long b) {
    asm("fma.rn.f32x2 %0, %1, %2, %0;" : "+l"(d) : "l"(a), "l"(b));
}
__device__ __forceinline__ void unpk2(float& lo, float& hi, unsigned long long v) {
    asm("mov.b64 {%0, %1}, %2;" : "=f"(lo), "=f"(hi) : "l"(v));
}

// ---------------------------------------------------------------------------
// Fused setup (one block per head): evolve U columns, build M_i, contract to C.
// ---------------------------------------------------------------------------
__global__ void build_all(const float* __restrict__ params) {
    int h = blockIdx.x;
    int tid = threadIdx.x;
    __shared__ float sUr[16][16];   // [col][row]
    __shared__ float sUi[16][16];
    __shared__ float sM[4][16][16];

    if (tid < 16) {
        int col = tid;
        float vr[16], vi[16];
#pragma unroll
        for (int i = 0; i < 16; i++) { vr[i] = 0.f; vi[i] = 0.f; }
        vr[col] = 1.f;

        for (int l = 0; l < 2; l++) {
#pragma unroll
            for (int q = 0; q < 4; q++) {
                const float* ph = params + ((h * 2 + l) * 4 + q) * 3;
                const int mask = 8 >> q;
                float c, s;
                __sincosf(0.5f * ph[0], &s, &c);   // RX
#pragma unroll
                for (int i = 0; i < 16; i++) {
                    if (!(i & mask)) {
                        int j = i | mask;
                        float ar0 = vr[i], ai0 = vi[i], ar1 = vr[j], ai1 = vi[j];
                        vr[i] = c * ar0 + s * ai1;
                        vi[i] = c * ai0 - s * ar1;
                        vr[j] = s * ai0 + c * ar1;
                        vi[j] = -s * ar0 + c * ai1;
                    }
                }
                __sincosf(0.5f * ph[1], &s, &c);   // RY
#pragma unroll
                for (int i = 0; i < 16; i++) {
                    if (!(i & mask)) {
                        int j = i | mask;
                        float ar0 = vr[i], ai0 = vi[i], ar1 = vr[j], ai1 = vi[j];
                        vr[i] = c * ar0 - s * ar1;
                        vi[i] = c * ai0 - s * ai1;
                        vr[j] = s * ar0 + c * ar1;
                        vi[j] = s * ai0 + c * ai1;
                    }
                }
                __sincosf(0.5f * ph[2], &s, &c);   // RZ
#pragma unroll
                for (int i = 0; i < 16; i++) {
                    if (!(i & mask)) {
                        int j = i | mask;
                        float ar0 = vr[i], ai0 = vi[i], ar1 = vr[j], ai1 = vi[j];
                        vr[i] = c * ar0 + s * ai0;
                        vi[i] = c * ai0 - s * ar0;
                        vr[j] = c * ar1 - s * ai1;
                        vi[j] = c * ai1 + s * ar1;
                    }
                }
            }
#pragma unroll
            for (int g = 0; g < 4; g++) {          // CNOT ring
                const int cbit = 8 >> g;
                const int tbit = 8 >> ((g + 1) & 3);
#pragma unroll
                for (int i = 0; i < 16; i++) {
                    if ((i & cbit) && !(i & tbit)) {
                        int j = i | tbit;
                        float tr = vr[i]; vr[i] = vr[j]; vr[j] = tr;
                        float ti = vi[i]; vi[i] = vi[j]; vi[j] = ti;
                    }
                }
            }
        }
#pragma unroll
        for (int r = 0; r < 16; r++) {
            sUr[col][r] = vr[r];
            sUi[col][r] = vi[r];
        }
    }
    __syncthreads();

    for (int e = tid; e < 4 * 256; e += blockDim.x) {
        int i = e >> 8;
        int j = (e >> 4) & 15;
        int k = e & 15;
        int zmask = 8 >> i;
        float acc = 0.f;
#pragma unroll
        for (int r = 0; r < 16; r++) {
            float t = sUr[j][r] * sUr[k][r] + sUi[j][r] * sUi[k][r];
            acc += (r & zmask) ? -t : t;
        }
        sM[i][j][k] = acc;
    }
    __syncthreads();

    for (int m = tid; m < 81; m += blockDim.x) {
        int p = m / 9, q = m % 9;
        int mq[4] = { p / 3, p % 3, q / 3, q % 3 };
        float c0 = 0.f, c1 = 0.f, c2 = 0.f, c3 = 0.f;
        for (int t = 0; t < 16; t++) {
            int j = 0, k = 0;
            float sgn = 1.f;
#pragma unroll
            for (int qq = 0; qq < 4; qq++) {
                int b = (t >> (3 - qq)) & 1;
                int jq, kq;
                if (mq[qq] == 0)      { jq = b; kq = b; }
                else if (mq[qq] == 1) { jq = b; kq = b; if (b) sgn = -sgn; }
                else                  { jq = b; kq = 1 - b; }
                j = (j << 1) | jq;
                k = (k << 1) | kq;
            }
            c0 += sgn * sM[0][j][k];
            c1 += sgn * sM[1][j][k];
            c2 += sgn * sM[2][j][k];
            c3 += sgn * sM[3][j][k];
        }
        float4* dst = reinterpret_cast<float4*>(g_C) + (h * 81 + m);
        *dst = make_float4(c0 * 0.0625f, c1 * 0.0625f,
                           c2 * 0.0625f, c3 * 0.0625f);
    }
}

// ---------------------------------------------------------------------------
// Main: block = 128 threads, 128 tokens, grid = 1024 (single full wave,
// 7 blocks/SM). Identical to round-13 best except the C stream is split
// across TWO independent hardware paths:
//   even p (5 rows) -> __ldg global (LSU floor 4/SMSP, 1 l1tex wf each,
//                      L1-resident after first touch)
//   odd  p (4 rows) -> __constant__ (LDC port, floor 8/SMSP)
// All indices compile-time (immediate offsets on both paths).
// Phase 2: block GEMM out = ev @ Wt + b; thread = 4 tokens x 8 outputs.
// ---------------------------------------------------------------------------
__global__ __launch_bounds__(128, 7) void qmha_main(
    const float* __restrict__ x,
    const float* __restrict__ W,      // [32][32] row-major
    const float* __restrict__ bvec,   // [32]
    float* __restrict__ out,
    int ntok)
{
    __shared__ float sEv[128 * 33];
    __shared__ __align__(16) float sWt[32 * 32];      // sWt[k*32+j] = W[j*32+k]
    __shared__ float sb[32];

    int tid = threadIdx.x;
    for (int i = tid; i < 1024; i += 128) {
        int k = i >> 5, j = i & 31;
        sWt[k * 32 + j] = W[j * 32 + k];
    }
    if (tid < 32) sb[tid] = bvec[tid];

    int base = blockIdx.x * 128;
    int t = base + tid;
    const float4* xt = reinterpret_cast<const float4*>(
        x + (size_t)(t < ntok ? t : 0) * 32);

    const ulonglong2* __restrict__ gC =
        reinterpret_cast<const ulonglong2*>(g_C);

    // ---- Phase 1: one token per thread, all heads (compile-time h) ----
#pragma unroll
    for (int h = 0; h < NH; h++) {
        float4 ang = xt[h];
        float c0, s0, c1, s1, c2, s2, c3, s3;
        __sincosf(ang.x, &s0, &c0);
        __sincosf(ang.y, &s1, &c1);
        __sincosf(ang.z, &s2, &c2);
        __sincosf(ang.w, &s3, &c3);

        // g01[p] rebuilt on the fly: u[p/3] * v[p%3]
        float u[3] = { 1.f, c0, s0 }, v[3] = { 1.f, c1, s1 };

        unsigned long long g23d[9];
        {
            float g23[9] = { 1.f, c3, s3, c2, c2*c3, c2*s3, s2, s2*c3, s2*s3 };
#pragma unroll
            for (int q = 0; q < 9; q++) g23d[q] = pk2(g23[q], g23[q]);
        }

        unsigned long long ev01 = 0ULL, ev23 = 0ULL;
#pragma unroll
        for (int p = 0; p < 9; p++) {
            unsigned long long t01 = 0ULL, t23 = 0ULL;
#pragma unroll
            for (int q = 0; q < 9; q++) {
                // h, p, q all compile-time -> immediate-offset loads.
                // Port split by p-parity: even p via L1/LSU (__ldg),
                // odd p via constant port (LDC).
                ulonglong2 cc;
                if ((p & 1) == 0) cc = __ldg(gC + (h * 81 + p * 9 + q));
                else              cc = c_C[h * 81 + p * 9 + q];
                fma2(t01, cc.x, g23d[q]);
                fma2(t23, cc.y, g23d[q]);
            }
            float g = u[p / 3] * v[p % 3];
            unsigned long long gp = pk2(g, g);
            fma2(ev01, gp, t01);
            fma2(ev23, gp, t23);
        }

        float e0, e1, e2, e3;
        unpk2(e0, e1, ev01);
        unpk2(e2, e3, ev23);
        sEv[tid * 33 + h * 4 + 0] = e0;
        sEv[tid * 33 + h * 4 + 1] = e1;
        sEv[tid * 33 + h * 4 + 2] = e2;
        sEv[tid * 33 + h * 4 + 3] = e3;
    }

    __syncthreads();

    // ---- Phase 2: out[128][32] = ev[128][32] @ sWt[32][32] + b ----
    int jg = tid & 3;        // output group of 8: columns jg*8 .. jg*8+7
    int tg = tid >> 2;       // token sub-index (0..31); tokens tg + 32*m

    unsigned long long acc[4][4];
#pragma unroll
    for (int m = 0; m < 4; m++)
#pragma unroll
        for (int c = 0; c < 4; c++)
            acc[m][c] = pk2(sb[jg * 8 + 2 * c], sb[jg * 8 + 2 * c + 1]);

#pragma unroll
    for (int k = 0; k < 32; k++) {
        const ulonglong2* w2 =
            reinterpret_cast<const ulonglong2*>(sWt + k * 32 + jg * 8);
        ulonglong2 wa = w2[0];   // outputs jg*8+0..3
        ulonglong2 wb = w2[1];   // outputs jg*8+4..7
#pragma unroll
        for (int m = 0; m < 4; m++) {
            float e = sEv[(tg + 32 * m) * 33 + k];  // bank (tg+k)%32, bcast x4
            unsigned long long ed = pk2(e, e);
            fma2(acc[m][0], ed, wa.x);
            fma2(acc[m][1], ed, wa.y);
            fma2(acc[m][2], ed, wb.x);
            fma2(acc[m][3], ed, wb.y);
        }
    }

#pragma unroll
    for (int m = 0; m < 4; m++) {
        int to = base + tg + 32 * m;
        if (to < ntok) {
            float4* o = reinterpret_cast<float4*>(out + (size_t)to * 32 + jg * 8);
            float a0, a1, a2, a3;
            unpk2(a0, a1, acc[m][0]);
            unpk2(a2, a3, acc[m][1]);
            o[0] = make_float4(a0, a1, a2, a3);
            unpk2(a0, a1, acc[m][2]);
            unpk2(a2, a3, acc[m][3]);
            o[1] = make_float4(a0, a1, a2, a3);
        }
    }
}

extern "C" void kernel_launch(void* const* d_in, const int* in_sizes, int n_in,
                              void* d_out, int out_size) {
    const float* x      = (const float*)d_in[0];  // [B,S,32]
    const float* params = (const float*)d_in[1];  // [8,2,4,3]
    const float* W      = (const float*)d_in[2];  // [32,32]
    const float* b      = (const float*)d_in[3];  // [32]
    float* out = (float*)d_out;

    int ntok = in_sizes[0] / 32;

    build_all<<<NH, 128>>>(params);

    // D2D memcpy into the constant bank (proven capturable).
    void* gC_ptr = nullptr;
    void* cC_ptr = nullptr;
    cudaGetSymbolAddress(&gC_ptr, g_C);
    cudaGetSymbolAddress(&cC_ptr, c_C);
    cudaMemcpyAsync(cC_ptr, gC_ptr, sizeof(float) * NH * 81 * 4,
                    cudaMemcpyDeviceToDevice, 0);

    int blocks = (ntok + 127) / 128;
    qmha_main<<<blocks, 128>>>(x, W, b, out, ntok);
}